// round 2
// baseline (speedup 1.0000x reference)
#include <cuda_runtime.h>
#include <math_constants.h>

#define BATCH 2
#define NP    4096
#define NQ    16384
#define FDIM  448            // 64 + 128 + 256
#define AGGP  720            // 707 padded to multiple of 16
#define NPTS  (BATCH * NQ)   // 32768 total query points
#define MPTS  (BATCH * NP)   // 8192 original points

// ---------------- scratch (device globals; no allocation allowed) ----------
__device__ float g_fall[MPTS * FDIM];          // point-major (f1|f2|f3)
__device__ int   g_gmax[BATCH * 256];          // global max (float bits, vals>=0)
__device__ int   g_knni[NPTS * 3];
__device__ float g_knnw[NPTS * 3];
__device__ float g_r1p[256 * AGGP];            // zero-padded r1 weights
__device__ float g_agg[NPTS * AGGP];
__device__ float g_h1[NPTS * 256];
__device__ float g_h2[NPTS * 128];
__device__ float g_h3[NPTS * 64];

#define FMA_F32X2(d, a, b, c) \
    asm("fma.rn.f32x2 %0, %1, %2, %3;" : "=l"(d) : "l"(a), "l"(b), "l"(c))

// ---------------- mlp1: 3 -> 64, warp per point, writes point-major ----------
__global__ void __launch_bounds__(256) mlp1_kernel(const float* __restrict__ op,
                                                   const float* __restrict__ w1,
                                                   const float* __restrict__ b1) {
    __shared__ float sw[192];
    __shared__ float sb[64];
    int t = threadIdx.x;
    if (t < 192) sw[t] = w1[t];
    if (t < 64)  sb[t] = b1[t];
    __syncthreads();
    int pfl  = blockIdx.x * 8 + (t >> 5);   // flat point 0..MPTS-1
    int lane = t & 31;
    int b  = pfl >> 12;
    int pt = pfl & (NP - 1);
    float x = op[b * 3 * NP + 0 * NP + pt];
    float y = op[b * 3 * NP + 1 * NP + pt];
    float z = op[b * 3 * NP + 2 * NP + pt];
    float* dst = g_fall + (size_t)pfl * FDIM;
#pragma unroll
    for (int u = 0; u < 2; u++) {
        int c = lane + u * 32;
        float v = fmaf(sw[c * 3 + 0], x, fmaf(sw[c * 3 + 1], y, fmaf(sw[c * 3 + 2], z, sb[c])));
        dst[c] = fmaxf(v, 0.0f);
    }
}

// ---------------- global max over f3 (point-major) ---------------------------
__global__ void gmax_zero_kernel() {
    int t = threadIdx.x + blockIdx.x * blockDim.x;
    if (t < BATCH * 256) g_gmax[t] = 0;   // relu outputs >= 0
}

__global__ void __launch_bounds__(256) gmax_kernel() {
    int c  = threadIdx.x;                 // channel 0..255
    int p0 = blockIdx.x * 128;            // flat point chunk (128 within one batch)
    int b  = p0 >> 12;
    float m = 0.0f;
    const float* src = g_fall + (size_t)p0 * FDIM + 192 + c;
#pragma unroll 4
    for (int p = 0; p < 128; p++) m = fmaxf(m, src[(size_t)p * FDIM]);
    atomicMax(&g_gmax[b * 256 + c], __float_as_int(m));
}

__global__ void pad_r1_kernel(const float* __restrict__ r1) {
    int tid = blockIdx.x * blockDim.x + threadIdx.x;   // over 256*AGGP
    if (tid >= 256 * AGGP) return;
    int r = tid / AGGP, k = tid - r * AGGP;
    g_r1p[tid] = (k < 707) ? r1[r * 707 + k] : 0.0f;
}

// ---------------- KNN (top-3), float4 smem (x,y,z,|o|^2), dot-form -----------
__global__ void __launch_bounds__(256) knn_kernel(const float* __restrict__ op,
                                                  const float* __restrict__ qp) {
    extern __shared__ float4 sp[];        // NP * 16B = 64 KB
    int b = blockIdx.y;
    int tid = threadIdx.x;
    for (int i = tid; i < NP; i += 256) {
        float x = op[b * 3 * NP + 0 * NP + i];
        float y = op[b * 3 * NP + 1 * NP + i];
        float z = op[b * 3 * NP + 2 * NP + i];
        sp[i] = make_float4(x, y, z, fmaf(x, x, fmaf(y, y, z * z)));
    }
    __syncthreads();

    int q = blockIdx.x * 256 + tid;
    float qx = qp[b * 3 * NQ + 0 * NQ + q];
    float qy = qp[b * 3 * NQ + 1 * NQ + q];
    float qz = qp[b * 3 * NQ + 2 * NQ + q];
    float nx = -2.0f * qx, ny = -2.0f * qy, nz = -2.0f * qz;

    // d' = |o|^2 - 2 o.q  (monotone with true distance; |q|^2 constant)
    float d0 = CUDART_INF_F, d1 = CUDART_INF_F, d2 = CUDART_INF_F;
    int i0 = 0, i1 = 0, i2 = 0;
#pragma unroll 8
    for (int j = 0; j < NP; j++) {
        float4 o = sp[j];
        float d = fmaf(o.x, nx, fmaf(o.y, ny, fmaf(o.z, nz, o.w)));
        if (d < d2) {
            if (d < d1) {
                d2 = d1; i2 = i1;
                if (d < d0) { d1 = d0; i1 = i0; d0 = d; i0 = j; }
                else        { d1 = d;  i1 = j; }
            } else { d2 = d; i2 = j; }
        }
    }
    // weights per reference: dist = sqrt(sum diff^2); w = (1/(dist+1e-8)) / sum
    int   ii[3] = {i0, i1, i2};
    float rc[3];
    float s = 0.0f;
#pragma unroll
    for (int k = 0; k < 3; k++) {
        float4 o = sp[ii[k]];
        float dx = o.x - qx, dy = o.y - qy, dz = o.z - qz;
        float dist = sqrtf(fmaf(dx, dx, fmaf(dy, dy, dz * dz)));
        rc[k] = 1.0f / (dist + 1e-8f);
        s += rc[k];
    }
    float inv = 1.0f / s;
    int base = (b * NQ + q) * 3;
#pragma unroll
    for (int k = 0; k < 3; k++) {
        g_knni[base + k] = ii[k];
        g_knnw[base + k] = rc[k] * inv;
    }
}

// ---------------- interp + concat into agg (warp per query) ------------------
__global__ void __launch_bounds__(256) agg_kernel(const float* __restrict__ qp) {
    int warp = blockIdx.x * 8 + (threadIdx.x >> 5);   // 0..NPTS-1
    int lane = threadIdx.x & 31;
    int b  = warp >> 14;
    int qi = warp & (NQ - 1);

    int   ik = 0; float wk = 0.0f;
    if (lane < 3) { ik = g_knni[warp * 3 + lane]; wk = g_knnw[warp * 3 + lane]; }
    int   ia = __shfl_sync(0xffffffffu, ik, 0);
    int   ib = __shfl_sync(0xffffffffu, ik, 1);
    int   ic = __shfl_sync(0xffffffffu, ik, 2);
    float wa = __shfl_sync(0xffffffffu, wk, 0);
    float wb = __shfl_sync(0xffffffffu, wk, 1);
    float wc = __shfl_sync(0xffffffffu, wk, 2);

    const float* fa = g_fall + (size_t)(b * NP + ia) * FDIM;
    const float* fb = g_fall + (size_t)(b * NP + ib) * FDIM;
    const float* fc = g_fall + (size_t)(b * NP + ic) * FDIM;
    float* ar = g_agg + (size_t)warp * AGGP;

    if (lane < 3) ar[lane] = qp[b * 3 * NQ + lane * NQ + qi];
#pragma unroll
    for (int c = lane; c < FDIM; c += 32)
        ar[3 + c] = wa * fa[c] + wb * fb[c] + wc * fc[c];
#pragma unroll
    for (int c = lane; c < 256; c += 32)
        ar[451 + c] = __int_as_float(g_gmax[b * 256 + c]);
    if (lane < 13) ar[707 + lane] = 0.0f;   // K padding
}

// ---------------- tiled SGEMM-NT with packed f32x2 FMA -----------------------
// C[m][n] = act(bias[n] + sum_k A[m][k] * W[n][k])
// BM=128, BN=64, BK=16, per-thread 8x4, 256 threads, reg double-buffered loads
template <bool RELU>
__global__ void __launch_bounds__(256) gemm_nt(const float* __restrict__ A, int lda,
                                               const float* __restrict__ W, int ldw,
                                               const float* __restrict__ bias,
                                               float* __restrict__ C, int ldc, int K) {
    __shared__ float As[16][132];   // [k][m], row = 528B (16B multiple)
    __shared__ float Wd[16][136];   // [k][2n] duplicated pairs, row = 544B
    const int t  = threadIdx.x;
    const int m0 = blockIdx.y * 128;
    const int n0 = blockIdx.x * 64;
    const int tx = t & 15;     // n group (4 cols)
    const int ty = t >> 4;     // m group (8 rows)

    const int arow0 = (t * 2 + 0) >> 2, akc0 = ((t * 2 + 0) & 3) * 4;
    const int arow1 = (t * 2 + 1) >> 2, akc1 = ((t * 2 + 1) & 3) * 4;
    const int wrow  = t >> 2,           wkc  = (t & 3) * 4;

    unsigned long long acc[4][4];
#pragma unroll
    for (int i = 0; i < 4; i++)
#pragma unroll
        for (int j = 0; j < 4; j++) acc[i][j] = 0ull;

    float4 ra0, ra1, rw;
    ra0 = *(const float4*)(A + (size_t)(m0 + arow0) * lda + akc0);
    ra1 = *(const float4*)(A + (size_t)(m0 + arow1) * lda + akc1);
    rw  = *(const float4*)(W + (size_t)(n0 + wrow) * ldw + wkc);

    for (int k0 = 0; k0 < K; k0 += 16) {
        // stage current tile to smem
        As[akc0 + 0][arow0] = ra0.x; As[akc0 + 1][arow0] = ra0.y;
        As[akc0 + 2][arow0] = ra0.z; As[akc0 + 3][arow0] = ra0.w;
        As[akc1 + 0][arow1] = ra1.x; As[akc1 + 1][arow1] = ra1.y;
        As[akc1 + 2][arow1] = ra1.z; As[akc1 + 3][arow1] = ra1.w;
        *(float2*)&Wd[wkc + 0][2 * wrow] = make_float2(rw.x, rw.x);
        *(float2*)&Wd[wkc + 1][2 * wrow] = make_float2(rw.y, rw.y);
        *(float2*)&Wd[wkc + 2][2 * wrow] = make_float2(rw.z, rw.z);
        *(float2*)&Wd[wkc + 3][2 * wrow] = make_float2(rw.w, rw.w);
        __syncthreads();

        if (k0 + 16 < K) {   // prefetch next tile into regs
            ra0 = *(const float4*)(A + (size_t)(m0 + arow0) * lda + k0 + 16 + akc0);
            ra1 = *(const float4*)(A + (size_t)(m0 + arow1) * lda + k0 + 16 + akc1);
            rw  = *(const float4*)(W + (size_t)(n0 + wrow) * ldw + k0 + 16 + wkc);
        }

#pragma unroll
        for (int kk = 0; kk < 16; kk++) {
            // a: 4 adjacent m-pairs; w: 4 duplicated n-values
            ulonglong2 a01 = *(const ulonglong2*)&As[kk][ty * 8];
            ulonglong2 a23 = *(const ulonglong2*)&As[kk][ty * 8 + 4];
            ulonglong2 w01 = *(const ulonglong2*)&Wd[kk][tx * 8];
            ulonglong2 w23 = *(const ulonglong2*)&Wd[kk][tx * 8 + 4];
            unsigned long long av[4] = {a01.x, a01.y, a23.x, a23.y};
            unsigned long long wv[4] = {w01.x, w01.y, w23.x, w23.y};
#pragma unroll
            for (int i = 0; i < 4; i++)
#pragma unroll
                for (int j = 0; j < 4; j++)
                    FMA_F32X2(acc[i][j], av[i], wv[j], acc[i][j]);
        }
        __syncthreads();
    }

    float bb[4];
#pragma unroll
    for (int j = 0; j < 4; j++) bb[j] = bias[n0 + tx * 4 + j];
#pragma unroll
    for (int i = 0; i < 4; i++) {
        float2 v0 = *(float2*)&acc[i][0];
        float2 v1 = *(float2*)&acc[i][1];
        float2 v2 = *(float2*)&acc[i][2];
        float2 v3 = *(float2*)&acc[i][3];
        float4 r0 = make_float4(v0.x + bb[0], v1.x + bb[1], v2.x + bb[2], v3.x + bb[3]);
        float4 r1 = make_float4(v0.y + bb[0], v1.y + bb[1], v2.y + bb[2], v3.y + bb[3]);
        if (RELU) {
            r0.x = fmaxf(r0.x, 0.0f); r0.y = fmaxf(r0.y, 0.0f);
            r0.z = fmaxf(r0.z, 0.0f); r0.w = fmaxf(r0.w, 0.0f);
            r1.x = fmaxf(r1.x, 0.0f); r1.y = fmaxf(r1.y, 0.0f);
            r1.z = fmaxf(r1.z, 0.0f); r1.w = fmaxf(r1.w, 0.0f);
        }
        int mrow = m0 + ty * 8 + 2 * i;
        *(float4*)(C + (size_t)mrow * ldc + n0 + tx * 4) = r0;
        *(float4*)(C + (size_t)(mrow + 1) * ldc + n0 + tx * 4) = r1;
    }
}

// ---------------- final layer: 64 -> 1 ---------------------------------------
__global__ void __launch_bounds__(256) final_kernel(const float* __restrict__ r4,
                                                    const float* __restrict__ rb4,
                                                    float* __restrict__ out) {
    __shared__ float s4[64];
    if (threadIdx.x < 64) s4[threadIdx.x] = r4[threadIdx.x];
    __syncthreads();
    int i = blockIdx.x * 256 + threadIdx.x;
    const float4* hp = (const float4*)(g_h3 + (size_t)i * 64);
    float acc = 0.0f;
#pragma unroll
    for (int j = 0; j < 16; j++) {
        float4 v = hp[j];
        acc += v.x * s4[4 * j + 0] + v.y * s4[4 * j + 1]
             + v.z * s4[4 * j + 2] + v.w * s4[4 * j + 3];
    }
    out[i] = acc + rb4[0];
}

// ---------------- launch -----------------------------------------------------
extern "C" void kernel_launch(void* const* d_in, const int* in_sizes, int n_in,
                              void* d_out, int out_size) {
    const float* op  = (const float*)d_in[0];
    const float* qp  = (const float*)d_in[1];
    const float* w1  = (const float*)d_in[2];
    const float* b1  = (const float*)d_in[3];
    const float* w2  = (const float*)d_in[4];
    const float* b2  = (const float*)d_in[5];
    const float* w3  = (const float*)d_in[6];
    const float* b3  = (const float*)d_in[7];
    const float* r1  = (const float*)d_in[8];
    const float* rb1 = (const float*)d_in[9];
    const float* r2  = (const float*)d_in[10];
    const float* rb2 = (const float*)d_in[11];
    const float* r3  = (const float*)d_in[12];
    const float* rb3 = (const float*)d_in[13];
    const float* r4  = (const float*)d_in[14];
    const float* rb4 = (const float*)d_in[15];
    float* out = (float*)d_out;

    float *p_fall, *p_h1, *p_h2, *p_h3, *p_agg, *p_r1p;
    cudaGetSymbolAddress((void**)&p_fall, g_fall);
    cudaGetSymbolAddress((void**)&p_h1,  g_h1);
    cudaGetSymbolAddress((void**)&p_h2,  g_h2);
    cudaGetSymbolAddress((void**)&p_h3,  g_h3);
    cudaGetSymbolAddress((void**)&p_agg, g_agg);
    cudaGetSymbolAddress((void**)&p_r1p, g_r1p);

    static bool knn_attr_set = false;
    if (!knn_attr_set) {
        cudaFuncSetAttribute(knn_kernel, cudaFuncAttributeMaxDynamicSharedMemorySize,
                             NP * (int)sizeof(float4));
        knn_attr_set = true;
    }

    // feature extractor (point-major throughout)
    gmax_zero_kernel<<<2, 256>>>();
    mlp1_kernel<<<MPTS / 8, 256>>>(op, w1, b1);
    // mlp2: 64 -> 128 as GEMM over 8192 points
    gemm_nt<true><<<dim3(128 / 64, MPTS / 128), 256>>>(p_fall, FDIM, w2, 64, b2,
                                                       p_fall + 64, FDIM, 64);
    // mlp3: 128 -> 256 as GEMM
    gemm_nt<true><<<dim3(256 / 64, MPTS / 128), 256>>>(p_fall + 64, FDIM, w3, 128, b3,
                                                       p_fall + 192, FDIM, 128);
    gmax_kernel<<<MPTS / 128, 256>>>();

    // knn + interpolation
    knn_kernel<<<dim3(NQ / 256, BATCH), 256, NP * sizeof(float4)>>>(op, qp);
    pad_r1_kernel<<<(256 * AGGP + 255) / 256, 256>>>(r1);
    agg_kernel<<<NPTS / 8, 256>>>(qp);

    // regressor
    gemm_nt<true><<<dim3(256 / 64, NPTS / 128), 256>>>(p_agg, AGGP, p_r1p, AGGP, rb1, p_h1, 256, AGGP);
    gemm_nt<true><<<dim3(128 / 64, NPTS / 128), 256>>>(p_h1, 256, r2, 256, rb2, p_h2, 128, 256);
    gemm_nt<true><<<dim3( 64 / 64, NPTS / 128), 256>>>(p_h2, 128, r3, 128, rb3, p_h3, 64, 128);
    final_kernel<<<NPTS / 256, 256>>>(r4, rb4, out);
}